// round 8
// baseline (speedup 1.0000x reference)
#include <cuda_runtime.h>
#include <cuda_fp16.h>
#include <cstdint>
#include <math.h>

// Problem constants (fixed instance)
#define NN 131072   // nodes
#define DD 128      // feature dim
#define GG 2048     // graphs
#define HH 512      // hidden
#define H4 2048     // 4*H
#define K2 1024     // 2*H (combined gemm K)

// ---------------- scratch (static device globals; no allocation) -------------
__device__ __half d_Wch[H4 * K2];      // combined gate weights [4H, 2H], fp16
__device__ float d_bias[H4];           // b_ih + b_hh
__device__ float d_gbias[H4];          // bias + h0 @ Wc[:, :H]^T  (t=1 shared part)
__device__ float d_Wmt[DD * HH];       // W_m transposed
__device__ __half d_xh[GG * K2];       // fp16 q_star = [h | r] (GEMM A operand)
__device__ __half d_fh[NN * DD];       // fp16 features
__device__ float d_c[GG * HH];         // LSTM cell state (t=1 -> t=2)
__device__ float d_h0[HH];             // shared h after t=0
__device__ float d_c0[HH];             // shared c after t=0
__device__ float d_u0[DD];             // shared u after t=0
__device__ float d_beta0[1];           // shared beta after t=0
__device__ float d_gates[GG * H4];     // gates scratch
__device__ float d_u[GG * DD];         // u_g = W_m^T h_g
__device__ float d_beta[GG];           // b_m . h_g
__device__ float d_s[GG * DD];         // s_g = sum_n a_n f_n (normalized)
__device__ float d_tg[GG];             // t_g = exp_sum/(exp_sum+eps)
__device__ int   d_start[GG + 1];      // segment offsets

// ------------------------------ prep kernels --------------------------------
__global__ void prep_wc(const float* __restrict__ W_ih, const float* __restrict__ W_hh) {
    int idx = blockIdx.x * 256 + threadIdx.x;
    if (idx >= H4 * K2) return;
    int j = idx >> 10, k = idx & 1023;
    float v = W_ih[idx];
    if (k < HH) v += W_hh[j * HH + k];
    d_Wch[idx] = __float2half(v);
}

__global__ void prep_misc(const float* __restrict__ b_ih, const float* __restrict__ b_hh,
                          const float* __restrict__ W_m) {
    int idx = blockIdx.x * 256 + threadIdx.x;
    if (idx < H4)      d_bias[idx] = b_ih[idx] + b_hh[idx];
    if (idx < DD * HH) {
        int d = idx >> 9, k = idx & 511;
        d_Wmt[idx] = W_m[k * DD + d];
    }
}

__global__ void feat2h(const float* __restrict__ f) {
    int idx = blockIdx.x * 256 + threadIdx.x;          // 1 thread = 8 floats
    const float4* f4 = (const float4*)f;
    float4 a = f4[idx * 2], b = f4[idx * 2 + 1];
    __half2 h0 = __floats2half2_rn(a.x, a.y);
    __half2 h1 = __floats2half2_rn(a.z, a.w);
    __half2 h2 = __floats2half2_rn(b.x, b.y);
    __half2 h3 = __floats2half2_rn(b.z, b.w);
    uint4 packed;
    packed.x = *(uint32_t*)&h0; packed.y = *(uint32_t*)&h1;
    packed.z = *(uint32_t*)&h2; packed.w = *(uint32_t*)&h3;
    ((uint4*)d_fh)[idx] = packed;
}

__global__ void graph_offsets(const int* __restrict__ gi) {
    int g = blockIdx.x * 256 + threadIdx.x;
    if (g > GG) return;
    int lo = 0, hi = NN;
    while (lo < hi) { int mid = (lo + hi) >> 1; if (gi[mid] < g) lo = mid + 1; else hi = mid; }
    d_start[g] = lo;
}

__device__ __forceinline__ float sigmoidf_(float x) { return 1.0f / (1.0f + expf(-x)); }

// ---- t=0: gates = bias identical across graphs -> one shared h0,c0,u0,beta0 --
__global__ __launch_bounds__(512) void init0(const float* __restrict__ W_m,
                                             const float* __restrict__ b_m) {
    __shared__ float h_s[HH];
    __shared__ float red[4][DD];
    __shared__ float br[512];
    int tid = threadIdx.x;                             // 0..511, = k
    float ig = d_bias[tid], fg = d_bias[HH + tid];
    float gg = d_bias[2 * HH + tid], og = d_bias[3 * HH + tid];
    float c = sigmoidf_(ig) * tanhf(gg);               // c_prev = 0
    float h = sigmoidf_(og) * tanhf(c);
    h_s[tid] = h;
    d_h0[tid] = h;
    d_c0[tid] = c;
    br[tid] = b_m[tid] * h;
    __syncthreads();
    // u0[d] = sum_k W_m[k,d] * h0[k]
    int d = tid & 127, q = tid >> 7;                   // q in 0..3
    float acc = 0.0f;
    for (int k = q * 128; k < q * 128 + 128; k++)
        acc += W_m[k * DD + d] * h_s[k];
    red[q][d] = acc;
    __syncthreads();
    if (tid < DD) d_u0[tid] = red[0][tid] + red[1][tid] + red[2][tid] + red[3][tid];
    // beta0 = b_m . h0
    for (int s = 256; s > 0; s >>= 1) {
        if (tid < s) br[tid] += br[tid + s];
        __syncthreads();
    }
    if (tid == 0) d_beta0[0] = br[0];
}

// gbias[j] = bias[j] + sum_{k<H} h0[k] * Wc[j,k]
__global__ __launch_bounds__(256) void compute_gbias() {
    int j = blockIdx.x * 8 + (threadIdx.x >> 5);
    int lane = threadIdx.x & 31;
    const __half2* w2 = (const __half2*)(d_Wch + (size_t)j * K2);
    const float2* h02 = (const float2*)d_h0;
    float p = 0.0f;
#pragma unroll
    for (int i = lane; i < HH / 2; i += 32) {
        float2 wf = __half22float2(w2[i]);
        float2 hf = h02[i];
        p += wf.x * hf.x + wf.y * hf.y;
    }
    p += __shfl_xor_sync(0xffffffffu, p, 16);
    p += __shfl_xor_sync(0xffffffffu, p, 8);
    p += __shfl_xor_sync(0xffffffffu, p, 4);
    p += __shfl_xor_sync(0xffffffffu, p, 2);
    p += __shfl_xor_sync(0xffffffffu, p, 1);
    if (lane == 0) d_gbias[j] = d_bias[j] + p;
}

// --------- gates GEMM (fp16 mma.sync m16n8k16): gates = xh @ Wch^T + bias ----
#define SROWH 40
#define A_STGH (128 * SROWH)
#define B_STGH (256 * SROWH)
#define GEMM_SMEM ((2 * A_STGH + 2 * B_STGH) * 2)

__device__ __forceinline__ void cpa16(uint32_t daddr, const void* g) {
    asm volatile("cp.async.cg.shared.global [%0], [%1], 16;" :: "r"(daddr), "l"(g));
}

__device__ __forceinline__ void load_stage(uint32_t sA, uint32_t sB,
                                           int bm, int bn, int k0, int tid) {
#pragma unroll
    for (int j = 0; j < 2; j++) {
        int a = tid + j * 256;
        int row = a >> 2, c = a & 3;
        cpa16(sA + (uint32_t)(row * SROWH + c * 8) * 2,
              d_xh + (size_t)(bm + row) * K2 + k0 + c * 8);
    }
#pragma unroll
    for (int j = 0; j < 4; j++) {
        int b = tid + j * 256;
        int row = b >> 2, c = b & 3;
        cpa16(sB + (uint32_t)(row * SROWH + c * 8) * 2,
              d_Wch + (size_t)(bn + row) * K2 + k0 + c * 8);
    }
    asm volatile("cp.async.commit_group;");
}

template <int KOFF, int KLEN, bool GB>
__global__ __launch_bounds__(256, 1) void gemm_h() {
    extern __shared__ __half smh[];
    __half* Abase = smh;
    __half* Bbase = smh + 2 * A_STGH;
    uint32_t sAu, sBu;
    {
        uint64_t t;
        asm("cvta.to.shared.u64 %0, %1;" : "=l"(t) : "l"(Abase));
        sAu = (uint32_t)t;
        asm("cvta.to.shared.u64 %0, %1;" : "=l"(t) : "l"(Bbase));
        sBu = (uint32_t)t;
    }
    const int tid = threadIdx.x, lane = tid & 31, warp = tid >> 5;
    const int wm = (warp & 1) * 64, wn = (warp >> 1) * 64;
    const int g = lane >> 2, t = lane & 3;
    const int bm = blockIdx.y * 128, bn = blockIdx.x * 256;

    float acc[4][8][4];
#pragma unroll
    for (int a = 0; a < 4; a++)
#pragma unroll
        for (int b = 0; b < 8; b++)
#pragma unroll
            for (int c = 0; c < 4; c++) acc[a][b][c] = 0.0f;

    load_stage(sAu, sBu, bm, bn, KOFF, tid);

    const int NIT = KLEN / 32;
    for (int it = 0; it < NIT; it++) {
        int buf = it & 1;
        if (it + 1 < NIT) {
            int nb = buf ^ 1;
            load_stage(sAu + nb * A_STGH * 2, sBu + nb * B_STGH * 2,
                       bm, bn, KOFF + (it + 1) * 32, tid);
            asm volatile("cp.async.wait_group 1;");
        } else {
            asm volatile("cp.async.wait_group 0;");
        }
        __syncthreads();

        const __half* Ab = Abase + buf * A_STGH;
        const __half* Bb = Bbase + buf * B_STGH;
#pragma unroll
        for (int kb = 0; kb < 32; kb += 16) {
            unsigned af[4][4], bf[8][2];
#pragma unroll
            for (int mi = 0; mi < 4; mi++) {
                const __half* ba = &Ab[(wm + mi * 16 + g) * SROWH + kb + 2 * t];
                af[mi][0] = *(const uint32_t*)(ba);
                af[mi][1] = *(const uint32_t*)(ba + 8 * SROWH);
                af[mi][2] = *(const uint32_t*)(ba + 8);
                af[mi][3] = *(const uint32_t*)(ba + 8 * SROWH + 8);
            }
#pragma unroll
            for (int ni = 0; ni < 8; ni++) {
                const __half* bb = &Bb[(wn + ni * 8 + g) * SROWH + kb + 2 * t];
                bf[ni][0] = *(const uint32_t*)(bb);
                bf[ni][1] = *(const uint32_t*)(bb + 8);
            }
#pragma unroll
            for (int mi = 0; mi < 4; mi++)
#pragma unroll
                for (int ni = 0; ni < 8; ni++)
                    asm volatile(
                        "mma.sync.aligned.m16n8k16.row.col.f32.f16.f16.f32 "
                        "{%0,%1,%2,%3}, {%4,%5,%6,%7}, {%8,%9}, {%0,%1,%2,%3};"
                        : "+f"(acc[mi][ni][0]), "+f"(acc[mi][ni][1]),
                          "+f"(acc[mi][ni][2]), "+f"(acc[mi][ni][3])
                        : "r"(af[mi][0]), "r"(af[mi][1]), "r"(af[mi][2]), "r"(af[mi][3]),
                          "r"(bf[ni][0]), "r"(bf[ni][1]));
        }
        __syncthreads();
    }

    const float* bias = GB ? d_gbias : d_bias;
#pragma unroll
    for (int mi = 0; mi < 4; mi++) {
        int r0 = bm + wm + mi * 16 + g;
#pragma unroll
        for (int ni = 0; ni < 8; ni++) {
            int cc = bn + wn + ni * 8 + 2 * t;
            float b0 = bias[cc], b1 = bias[cc + 1];
            float2 v0 = make_float2(acc[mi][ni][0] + b0, acc[mi][ni][1] + b1);
            float2 v1 = make_float2(acc[mi][ni][2] + b0, acc[mi][ni][3] + b1);
            *(float2*)&d_gates[(size_t)r0 * H4 + cc] = v0;
            *(float2*)&d_gates[(size_t)(r0 + 8) * H4 + cc] = v1;
        }
    }
}

// ------- fused LSTM + u + beta: 16 graphs / block, 256 threads ---------------
__global__ __launch_bounds__(256) void lstm_u_beta(int use_c0, int wc,
                                                   const float* __restrict__ W_m,
                                                   const float* __restrict__ b_m,
                                                   float* __restrict__ out, int wout) {
    __shared__ float h_s[16][HH];                      // 32 KB
    __shared__ float red[2][16][DD];                   // 16 KB
    int g0 = blockIdx.x * 16;
    int tid = threadIdx.x;
    int k2 = tid * 2;                                  // this thread's k pair

    const float* cbase = use_c0 ? d_c0 : d_c;
    size_t cstride = use_c0 ? 0 : HH;

    // ---- phase 1: LSTM for 16 graphs, 2 cells each ----
#pragma unroll
    for (int gg = 0; gg < 16; gg++) {
        int g = g0 + gg;
        const float* row = d_gates + (size_t)g * H4;
        float2 ig = *(const float2*)(row + k2);
        float2 fg = *(const float2*)(row + HH + k2);
        float2 gv = *(const float2*)(row + 2 * HH + k2);
        float2 og = *(const float2*)(row + 3 * HH + k2);
        float2 cp = *(const float2*)(cbase + (size_t)g * cstride + k2);
        float c0n = sigmoidf_(fg.x) * cp.x + sigmoidf_(ig.x) * tanhf(gv.x);
        float c1n = sigmoidf_(fg.y) * cp.y + sigmoidf_(ig.y) * tanhf(gv.y);
        float h0n = sigmoidf_(og.x) * tanhf(c0n);
        float h1n = sigmoidf_(og.y) * tanhf(c1n);
        *(float2*)&h_s[gg][k2] = make_float2(h0n, h1n);
        __half2* xh2 = (__half2*)(d_xh + (size_t)g * K2 + k2);
        *xh2 = __floats2half2_rn(h0n, h1n);
        if (wc) *(float2*)&d_c[(size_t)g * HH + k2] = make_float2(c0n, c1n);
        if (wout) *(float2*)&out[(size_t)g * K2 + k2] = make_float2(h0n, h1n);
    }
    __syncthreads();

    // ---- phase 2: u_g = W_m^T h_g  (d = tid&127, k half by tid>>7) ----
    {
        int d = tid & 127, kh = tid >> 7;
        int kb = kh * 256;
        float acc[16];
#pragma unroll
        for (int gg = 0; gg < 16; gg++) acc[gg] = 0.0f;
        for (int k = 0; k < 256; k += 2) {
            float w0 = W_m[(kb + k) * DD + d];
            float w1 = W_m[(kb + k + 1) * DD + d];
#pragma unroll
            for (int gg = 0; gg < 16; gg++) {
                float2 hv = *(const float2*)&h_s[gg][kb + k];
                acc[gg] += w0 * hv.x + w1 * hv.y;
            }
        }
#pragma unroll
        for (int gg = 0; gg < 16; gg++) red[kh][gg][d] = acc[gg];
    }
    __syncthreads();
#pragma unroll
    for (int j = 0; j < 8; j++) {
        int e = tid + j * 256;                         // 2048 outputs
        int gg = e >> 7, dd = e & 127;
        d_u[(g0 + gg) * DD + dd] = red[0][gg][dd] + red[1][gg][dd];
    }

    // ---- phase 3: beta = b_m . h (2 graphs per warp) ----
    {
        int w = tid >> 5, lane = tid & 31;
#pragma unroll
        for (int j = 0; j < 2; j++) {
            int gg = w * 2 + j;
            float p = 0.0f;
            for (int k = lane; k < HH; k += 32) p += b_m[k] * h_s[gg][k];
            p += __shfl_xor_sync(0xffffffffu, p, 16);
            p += __shfl_xor_sync(0xffffffffu, p, 8);
            p += __shfl_xor_sync(0xffffffffu, p, 4);
            p += __shfl_xor_sync(0xffffffffu, p, 2);
            p += __shfl_xor_sync(0xffffffffu, p, 1);
            if (lane == 0) d_beta[g0 + gg] = p;
        }
    }
}

// ------- fused attention: online softmax, 4 nodes per warp iteration ---------
__global__ __launch_bounds__(256) void attention_fused(int use_u0) {
    int g = blockIdx.x;
    int s0 = d_start[g], s1 = d_start[g + 1];
    __shared__ __align__(16) float u_s[128];
    __shared__ __align__(16) float wacc[8][128];
    __shared__ float wm_s[8], wS_s[8], fac_s[8];
    __shared__ float inv_s;
    int tid = threadIdx.x, lane = tid & 31, warp = tid >> 5;

    if (tid < 128) u_s[tid] = use_u0 ? d_u0[tid] : d_u[g * DD + tid];
    float beta = use_u0 ? d_beta0[0] : d_beta[g];
    __syncthreads();

    float4 uv = ((const float4*)u_s)[lane];
    float m = -3.4e38f, S = 0.0f;
    float4 acc = make_float4(0.f, 0.f, 0.f, 0.f);

    for (int base = s0 + warp * 4; base < s1; base += 32) {
        float4 fv[4];
        float e[4];
#pragma unroll
        for (int j = 0; j < 4; j++) {
            int n = base + j;
            if (n < s1) {
                uint2 raw = *(const uint2*)(d_fh + (size_t)n * DD + lane * 4);
                float2 f01 = __half22float2(*(__half2*)&raw.x);
                float2 f23 = __half22float2(*(__half2*)&raw.y);
                fv[j] = make_float4(f01.x, f01.y, f23.x, f23.y);
            } else {
                fv[j] = make_float4(0.f, 0.f, 0.f, 0.f);
            }
            e[j] = fv[j].x * uv.x + fv[j].y * uv.y + fv[j].z * uv.z + fv[j].w * uv.w;
        }
        // 4 independent warp reductions (interleaved by the scheduler)
#pragma unroll
        for (int j = 0; j < 4; j++) {
            e[j] += __shfl_xor_sync(0xffffffffu, e[j], 16);
            e[j] += __shfl_xor_sync(0xffffffffu, e[j], 8);
            e[j] += __shfl_xor_sync(0xffffffffu, e[j], 4);
            e[j] += __shfl_xor_sync(0xffffffffu, e[j], 2);
            e[j] += __shfl_xor_sync(0xffffffffu, e[j], 1);
        }
#pragma unroll
        for (int j = 0; j < 4; j++)
            e[j] = (base + j < s1) ? e[j] + beta : -3.0e38f;

        float m4 = fmaxf(fmaxf(e[0], e[1]), fmaxf(e[2], e[3]));
        float w0 = __expf(e[0] - m4), w1 = __expf(e[1] - m4);
        float w2 = __expf(e[2] - m4), w3 = __expf(e[3] - m4);
        float S4 = (w0 + w1) + (w2 + w3);
        float4 a4;
        a4.x = w0 * fv[0].x + w1 * fv[1].x + w2 * fv[2].x + w3 * fv[3].x;
        a4.y = w0 * fv[0].y + w1 * fv[1].y + w2 * fv[2].y + w3 * fv[3].y;
        a4.z = w0 * fv[0].z + w1 * fv[1].z + w2 * fv[2].z + w3 * fv[3].z;
        a4.w = w0 * fv[0].w + w1 * fv[1].w + w2 * fv[2].w + w3 * fv[3].w;

        float mn = fmaxf(m, m4);
        float al = __expf(m - mn);
        float bl = __expf(m4 - mn);
        S = S * al + S4 * bl;
        acc.x = acc.x * al + a4.x * bl;
        acc.y = acc.y * al + a4.y * bl;
        acc.z = acc.z * al + a4.z * bl;
        acc.w = acc.w * al + a4.w * bl;
        m = mn;
    }
    if (lane == 0) { wm_s[warp] = m; wS_s[warp] = S; }
    ((float4*)wacc[warp])[lane] = acc;
    __syncthreads();

    if (tid == 0) {
        float M = -3.4e38f;
#pragma unroll
        for (int w = 0; w < 8; w++)
            if (wS_s[w] > 0.0f) M = fmaxf(M, wm_s[w]);
        float Z = 0.0f;
#pragma unroll
        for (int w = 0; w < 8; w++) {
            float sc = (wS_s[w] > 0.0f) ? __expf(wm_s[w] - M) : 0.0f;
            fac_s[w] = sc;
            Z += sc * wS_s[w];
        }
        float inv = 1.0f / (Z + 1e-7f);
        inv_s = inv;
        d_tg[g] = Z * inv;
    }
    __syncthreads();

    if (tid < 128) {
        float inv = inv_s;
        float s = 0.0f;
#pragma unroll
        for (int w = 0; w < 8; w++) s += wacc[w][tid] * fac_s[w];
        d_s[g * DD + tid] = s * inv;
    }
}

// ---------------- r_g = W_m s_g + t_g b_m  (8 graphs / block) ----------------
__global__ __launch_bounds__(512) void compute_r(const float* __restrict__ b_m,
                                                 float* __restrict__ out, int wout) {
    int g0 = blockIdx.x * 8;
    int k = threadIdx.x;                              // 0..511
    __shared__ float ss[8][128];
    {
        int i = k;        ss[i >> 7][i & 127] = d_s[(g0 + (i >> 7)) * DD + (i & 127)];
        int i2 = k + 512; ss[i2 >> 7][i2 & 127] = d_s[(g0 + (i2 >> 7)) * DD + (i2 & 127)];
    }
    __syncthreads();
    float bm = b_m[k];
    float acc[8];
#pragma unroll
    for (int gg = 0; gg < 8; gg++) acc[gg] = d_tg[g0 + gg] * bm;
    for (int d = 0; d < DD; d++) {
        float w = d_Wmt[d * HH + k];
#pragma unroll
        for (int gg = 0; gg < 8; gg++) acc[gg] += w * ss[gg][d];
    }
#pragma unroll
    for (int gg = 0; gg < 8; gg++) {
        d_xh[(g0 + gg) * K2 + HH + k] = __float2half(acc[gg]);
        if (wout) out[(g0 + gg) * K2 + HH + k] = acc[gg];
    }
}

// ------------------------------ launcher ------------------------------------
extern "C" void kernel_launch(void* const* d_in, const int* in_sizes, int n_in,
                              void* d_out, int out_size) {
    const float* features = (const float*)d_in[0];
    const int*   gi       = (const int*)d_in[1];
    const float* W_m      = (const float*)d_in[2];
    const float* b_m      = (const float*)d_in[3];
    const float* W_ih     = (const float*)d_in[4];
    const float* W_hh     = (const float*)d_in[5];
    const float* b_ih     = (const float*)d_in[6];
    const float* b_hh     = (const float*)d_in[7];
    float* out = (float*)d_out;

    cudaFuncSetAttribute(gemm_h<512, 512, true>,
                         cudaFuncAttributeMaxDynamicSharedMemorySize, GEMM_SMEM);
    cudaFuncSetAttribute(gemm_h<0, 1024, false>,
                         cudaFuncAttributeMaxDynamicSharedMemorySize, GEMM_SMEM);

    prep_wc<<<(H4 * K2) / 256, 256>>>(W_ih, W_hh);
    prep_misc<<<(DD * HH) / 256, 256>>>(b_ih, b_hh, W_m);
    graph_offsets<<<(GG + 1 + 255) / 256, 256>>>(gi);
    feat2h<<<(NN * DD / 8) / 256, 256>>>(features);

    // t = 0 (all graphs share h0/c0/u0/beta0; attention reads them directly)
    init0<<<1, 512>>>(W_m, b_m);
    attention_fused<<<GG, 256>>>(1);
    compute_r<<<GG / 8, 512>>>(b_m, out, 0);

    // t = 1 (K=512 GEMM on r only; h0 folded into gbias; c from shared c0)
    compute_gbias<<<GG / 8, 256>>>();
    gemm_h<512, 512, true><<<dim3(H4 / 256, GG / 128), 256, GEMM_SMEM>>>();
    lstm_u_beta<<<GG / 16, 256>>>(1, 1, W_m, b_m, out, 0);
    attention_fused<<<GG, 256>>>(0);
    compute_r<<<GG / 8, 512>>>(b_m, out, 0);

    // t = 2 (full K=1024 GEMM; final outputs)
    gemm_h<0, 1024, false><<<dim3(H4 / 256, GG / 128), 256, GEMM_SMEM>>>();
    lstm_u_beta<<<GG / 16, 256>>>(0, 0, W_m, b_m, out, 1);
    attention_fused<<<GG, 256>>>(0);
    compute_r<<<GG / 8, 512>>>(b_m, out, 1);
}

// round 9
// speedup vs baseline: 1.1645x; 1.1645x over previous
#include <cuda_runtime.h>
#include <cuda_fp16.h>
#include <cstdint>
#include <math.h>

// Problem constants (fixed instance)
#define NN 131072   // nodes
#define DD 128      // feature dim
#define GG 2048     // graphs
#define HH 512      // hidden
#define H4 2048     // 4*H
#define K2 1024     // 2*H

// ---------------- scratch (static device globals; no allocation) -------------
__device__ __half d_Wch[H4 * K2];      // gate weights, rows permuted nj=4k+gate
__device__ float d_bias4f[H4];         // permuted bias: [k*4+gate]
__device__ float d_gbias4f[H4];        // permuted bias + h0 contribution (t=1)
__device__ float d_Wmt[DD * HH];       // W_m transposed
__device__ __half d_xh[GG * K2];       // fp16 q_star = [h | r] (GEMM A operand)
__device__ __half d_fh[NN * DD];       // fp16 features
__device__ float d_c[GG * HH];         // LSTM cell state (t=1 -> t=2)
__device__ float d_hf[GG * HH];        // fp32 h (GEMM epilogue -> u_beta)
__device__ float d_h0[HH];             // shared h after t=0
__device__ float d_c0[HH];             // shared c after t=0
__device__ float d_u0[DD];             // shared u after t=0
__device__ float d_beta0[1];           // shared beta after t=0
__device__ float d_u[GG * DD];         // u_g = W_m^T h_g
__device__ float d_beta[GG];           // b_m . h_g
__device__ float d_s[GG * DD];         // s_g (normalized weighted feature sum)
__device__ float d_tg[GG];             // exp_sum/(exp_sum+eps)
__device__ int   d_start[GG + 1];      // segment offsets

__device__ __forceinline__ float fsig(float x) {
    return __fdividef(1.0f, 1.0f + __expf(-x));
}
__device__ __forceinline__ float ftanh(float x) {
    return __fdividef(2.0f, 1.0f + __expf(-2.0f * x)) - 1.0f;
}

// ---------------- prep_all: everything independent, one launch ---------------
// blocks: [0,8192) feat2h | [8192,16384) weight perm | 256 Wmt | 2 bias4 |
//         9 graph offsets | 1 init0
#define B_FEAT 8192
#define B_WC   8192
#define B_WMT  256
#define B_B4   2
#define B_OFF  9
#define PREP_BLOCKS (B_FEAT + B_WC + B_WMT + B_B4 + B_OFF + 1)

__global__ __launch_bounds__(256) void prep_all(
    const float* __restrict__ f, const float* __restrict__ W_ih,
    const float* __restrict__ W_hh, const float* __restrict__ b_ih,
    const float* __restrict__ b_hh, const float* __restrict__ W_m,
    const float* __restrict__ b_m, const int* __restrict__ gi) {
    int b = blockIdx.x;
    int tid = threadIdx.x;
    if (b < B_FEAT) {                       // features -> fp16
        int idx = b * 256 + tid;            // 1 thread = 8 floats
        const float4* f4 = (const float4*)f;
        float4 a = f4[idx * 2], bb = f4[idx * 2 + 1];
        __half2 h0 = __floats2half2_rn(a.x, a.y);
        __half2 h1 = __floats2half2_rn(a.z, a.w);
        __half2 h2 = __floats2half2_rn(bb.x, bb.y);
        __half2 h3 = __floats2half2_rn(bb.z, bb.w);
        uint4 packed;
        packed.x = *(uint32_t*)&h0; packed.y = *(uint32_t*)&h1;
        packed.z = *(uint32_t*)&h2; packed.w = *(uint32_t*)&h3;
        ((uint4*)d_fh)[idx] = packed;
        return;
    }
    b -= B_FEAT;
    if (b < B_WC) {                         // combined weights, permuted rows
        int idx = b * 256 + tid;            // j*1024 + col
        int j = idx >> 10, col = idx & 1023;
        float v = W_ih[idx];
        if (col < HH) v += W_hh[j * HH + col];
        int nj = 4 * (j & 511) + (j >> 9);
        d_Wch[(size_t)nj * K2 + col] = __float2half(v);
        return;
    }
    b -= B_WC;
    if (b < B_WMT) {                        // W_m transposed
        int idx = b * 256 + tid;
        int d = idx >> 9, k = idx & 511;
        d_Wmt[idx] = W_m[k * DD + d];
        return;
    }
    b -= B_WMT;
    if (b < B_B4) {                         // permuted bias float4 per k
        int k = b * 256 + tid;
        float4 v;
        v.x = b_ih[k] + b_hh[k];
        v.y = b_ih[HH + k] + b_hh[HH + k];
        v.z = b_ih[2 * HH + k] + b_hh[2 * HH + k];
        v.w = b_ih[3 * HH + k] + b_hh[3 * HH + k];
        ((float4*)d_bias4f)[k] = v;
        return;
    }
    b -= B_B4;
    if (b < B_OFF) {                        // segment offsets (sorted index)
        int g = b * 256 + tid;
        if (g > GG) return;
        int lo = 0, hi = NN;
        while (lo < hi) { int mid = (lo + hi) >> 1; if (gi[mid] < g) lo = mid + 1; else hi = mid; }
        d_start[g] = lo;
        return;
    }
    // ---- init0: t=0 shared h0/c0/u0/beta0 (gates = bias for every graph) ----
    {
        __shared__ float h_s[HH];
        __shared__ float br[256];
        float bsum = 0.0f;
#pragma unroll
        for (int q = 0; q < 2; q++) {
            int k = tid + q * 256;
            float big = b_ih[k] + b_hh[k];
            float bgg = b_ih[2 * HH + k] + b_hh[2 * HH + k];
            float bog = b_ih[3 * HH + k] + b_hh[3 * HH + k];
            float c = fsig(big) * ftanh(bgg);          // c_prev = 0
            float h = fsig(bog) * ftanh(c);
            h_s[k] = h;
            d_h0[k] = h;
            d_c0[k] = c;
            bsum += b_m[k] * h;
        }
        br[tid] = bsum;
        __syncthreads();
        if (tid < DD) {                     // u0[d] = sum_k W_m[k,d]*h0[k]
            float a = 0.0f;
            for (int k = 0; k < HH; k++) a += W_m[k * DD + tid] * h_s[k];
            d_u0[tid] = a;
        }
        for (int s = 128; s > 0; s >>= 1) {
            if (tid < s) br[tid] += br[tid + s];
            __syncthreads();
        }
        if (tid == 0) d_beta0[0] = br[0];
    }
}

// ------ gates GEMM (fp16 mma.sync m16n8k16) + fused LSTM epilogue ------------
// CTA 128(M=graphs) x 256(N=4 gates interleaved by k), BK=32, double buffer.
// Column c of output = gate (c&3) of hidden unit k=(c>>2). Epilogue exchanges
// gate halves between thread pairs (shfl_xor 1), runs the LSTM cell, stages
// h (and c) in smem, and writes coalesced to d_hf / d_xh / d_c / out.
#define SROWH 40
#define A_STGH (128 * SROWH)
#define B_STGH (256 * SROWH)
#define EPI_STRIDE 68                   // floats per staged row (64 + pad)
#define GEMM_SMEM (2 * 128 * EPI_STRIDE * 4 > (2 * A_STGH + 2 * B_STGH) * 2 ? \
                   2 * 128 * EPI_STRIDE * 4 : (2 * A_STGH + 2 * B_STGH) * 2)

__device__ __forceinline__ void cpa16(uint32_t daddr, const void* g) {
    asm volatile("cp.async.cg.shared.global [%0], [%1], 16;" :: "r"(daddr), "l"(g));
}

__device__ __forceinline__ void load_stage(uint32_t sA, uint32_t sB,
                                           int bm, int bn, int k0, int tid) {
#pragma unroll
    for (int j = 0; j < 2; j++) {
        int a = tid + j * 256;
        int row = a >> 2, c = a & 3;
        cpa16(sA + (uint32_t)(row * SROWH + c * 8) * 2,
              d_xh + (size_t)(bm + row) * K2 + k0 + c * 8);
    }
#pragma unroll
    for (int j = 0; j < 4; j++) {
        int b = tid + j * 256;
        int row = b >> 2, c = b & 3;
        cpa16(sB + (uint32_t)(row * SROWH + c * 8) * 2,
              d_Wch + (size_t)(bn + row) * K2 + k0 + c * 8);
    }
    asm volatile("cp.async.commit_group;");
}

// FIRST=true : t=1 (KOFF=512,KLEN=512): gbias + shared c0, writes c,xh,hf
// FIRST=false: t=2 (KOFF=0,KLEN=1024) : bias + per-graph c,   writes hf,out
template <int KOFF, int KLEN, bool FIRST>
__global__ __launch_bounds__(256, 1) void gemm_lstm(float* __restrict__ out) {
    extern __shared__ __half smh[];
    __half* Abase = smh;
    __half* Bbase = smh + 2 * A_STGH;
    uint32_t sAu, sBu;
    {
        uint64_t t;
        asm("cvta.to.shared.u64 %0, %1;" : "=l"(t) : "l"(Abase));
        sAu = (uint32_t)t;
        asm("cvta.to.shared.u64 %0, %1;" : "=l"(t) : "l"(Bbase));
        sBu = (uint32_t)t;
    }
    const int tid = threadIdx.x, lane = tid & 31, warp = tid >> 5;
    const int wm = (warp & 1) * 64, wn = (warp >> 1) * 64;
    const int g = lane >> 2, t = lane & 3;
    const int bm = blockIdx.y * 128, bn = blockIdx.x * 256;

    float acc[4][8][4];
#pragma unroll
    for (int a = 0; a < 4; a++)
#pragma unroll
        for (int b = 0; b < 8; b++)
#pragma unroll
            for (int c = 0; c < 4; c++) acc[a][b][c] = 0.0f;

    load_stage(sAu, sBu, bm, bn, KOFF, tid);

    const int NIT = KLEN / 32;
    for (int it = 0; it < NIT; it++) {
        int buf = it & 1;
        if (it + 1 < NIT) {
            int nb = buf ^ 1;
            load_stage(sAu + nb * A_STGH * 2, sBu + nb * B_STGH * 2,
                       bm, bn, KOFF + (it + 1) * 32, tid);
            asm volatile("cp.async.wait_group 1;");
        } else {
            asm volatile("cp.async.wait_group 0;");
        }
        __syncthreads();

        const __half* Ab = Abase + buf * A_STGH;
        const __half* Bb = Bbase + buf * B_STGH;
#pragma unroll
        for (int kb = 0; kb < 32; kb += 16) {
            unsigned af[4][4], bf[8][2];
#pragma unroll
            for (int mi = 0; mi < 4; mi++) {
                const __half* ba = &Ab[(wm + mi * 16 + g) * SROWH + kb + 2 * t];
                af[mi][0] = *(const uint32_t*)(ba);
                af[mi][1] = *(const uint32_t*)(ba + 8 * SROWH);
                af[mi][2] = *(const uint32_t*)(ba + 8);
                af[mi][3] = *(const uint32_t*)(ba + 8 * SROWH + 8);
            }
#pragma unroll
            for (int ni = 0; ni < 8; ni++) {
                const __half* bb = &Bb[(wn + ni * 8 + g) * SROWH + kb + 2 * t];
                bf[ni][0] = *(const uint32_t*)(bb);
                bf[ni][1] = *(const uint32_t*)(bb + 8);
            }
#pragma unroll
            for (int mi = 0; mi < 4; mi++)
#pragma unroll
                for (int ni = 0; ni < 8; ni++)
                    asm volatile(
                        "mma.sync.aligned.m16n8k16.row.col.f32.f16.f16.f32 "
                        "{%0,%1,%2,%3}, {%4,%5,%6,%7}, {%8,%9}, {%0,%1,%2,%3};"
                        : "+f"(acc[mi][ni][0]), "+f"(acc[mi][ni][1]),
                          "+f"(acc[mi][ni][2]), "+f"(acc[mi][ni][3])
                        : "r"(af[mi][0]), "r"(af[mi][1]), "r"(af[mi][2]), "r"(af[mi][3]),
                          "r"(bf[ni][0]), "r"(bf[ni][1]));
        }
        __syncthreads();
    }

    // ---------------- fused LSTM epilogue ----------------
    float* hbuf = (float*)smh;                       // [128][EPI_STRIDE]
    float* cbuf = hbuf + 128 * EPI_STRIDE;
    const int kb0 = bn >> 2;                         // first k of CTA tile
    const float4* b4p = (const float4*)(FIRST ? d_gbias4f : d_bias4f);

    if (!FIRST) {                                    // preload c tile, coalesced
        int r = tid >> 1, kh = (tid & 1) * 32;
        const float4* src = (const float4*)(d_c + (size_t)(bm + r) * HH + kb0 + kh);
#pragma unroll
        for (int j = 0; j < 8; j++) {
            float4 v = src[j];
            float* dst = &cbuf[r * EPI_STRIDE + kh + 4 * j];
            dst[0] = v.x; dst[1] = v.y; dst[2] = v.z; dst[3] = v.w;
        }
        __syncthreads();
    }

    {
        const int kwarp = (bn + wn) >> 2;
        const bool odd = t & 1;
        const int khalf = t >> 1;
#pragma unroll
        for (int ni = 0; ni < 8; ni++) {
            int k = kwarp + ni * 2 + khalf;
            float4 b4 = b4p[k];
            float blo = odd ? b4.z : b4.x;
            float bhi = odd ? b4.w : b4.y;
            float cp_sh = FIRST ? d_c0[k] : 0.0f;
            int klocal = k - kb0;
#pragma unroll
            for (int mi = 0; mi < 4; mi++) {
                float a0 = acc[mi][ni][0] + blo;
                float a1 = acc[mi][ni][1] + bhi;
                float a2 = acc[mi][ni][2] + blo;
                float a3 = acc[mi][ni][3] + bhi;
                float slo = odd ? a0 : a2;
                float shi = odd ? a1 : a3;
                float rlo = __shfl_xor_sync(0xffffffffu, slo, 1);
                float rhi = __shfl_xor_sync(0xffffffffu, shi, 1);
                float iv = odd ? rlo : a0;
                float fv = odd ? rhi : a1;
                float gv = odd ? a2 : rlo;
                float ov = odd ? a3 : rhi;
                int rlocal = wm + mi * 16 + g + (odd ? 8 : 0);
                float cp = FIRST ? cp_sh : cbuf[rlocal * EPI_STRIDE + klocal];
                float cn = fsig(fv) * cp + fsig(iv) * ftanh(gv);
                float h = fsig(ov) * ftanh(cn);
                hbuf[rlocal * EPI_STRIDE + klocal] = h;
                if (FIRST) cbuf[rlocal * EPI_STRIDE + klocal] = cn;
            }
        }
    }
    __syncthreads();

    {   // coalesced writeout of the 128x64 tile
        int r = tid >> 1, kh = (tid & 1) * 32;
        int row = bm + r;
        int kg = kb0 + kh;
#pragma unroll
        for (int j = 0; j < 8; j++) {
            const float* hsrc = &hbuf[r * EPI_STRIDE + kh + 4 * j];
            float4 v = make_float4(hsrc[0], hsrc[1], hsrc[2], hsrc[3]);
            *(float4*)(d_hf + (size_t)row * HH + kg + 4 * j) = v;
            if (FIRST) {
                __half2 p0 = __floats2half2_rn(v.x, v.y);
                __half2 p1 = __floats2half2_rn(v.z, v.w);
                uint2 u; u.x = *(uint32_t*)&p0; u.y = *(uint32_t*)&p1;
                *(uint2*)(d_xh + (size_t)row * K2 + kg + 4 * j) = u;
                const float* csrc = &cbuf[r * EPI_STRIDE + kh + 4 * j];
                float4 cv = make_float4(csrc[0], csrc[1], csrc[2], csrc[3]);
                *(float4*)(d_c + (size_t)row * HH + kg + 4 * j) = cv;
            } else {
                *(float4*)(out + (size_t)row * K2 + kg + 4 * j) = v;
            }
        }
    }
}

// ------- u_beta: u_g = W_m^T h_g, beta_g = b_m . h_g (16 graphs / block) -----
__global__ __launch_bounds__(256) void u_beta(const float* __restrict__ W_m,
                                              const float* __restrict__ b_m) {
    __shared__ float h_s[16][HH];                      // 32 KB
    __shared__ float red[2][16][DD];                   // 16 KB
    int g0 = blockIdx.x * 16;
    int tid = threadIdx.x;

    const float4* src = (const float4*)(d_hf + (size_t)g0 * HH);
    float4* dst = (float4*)h_s;
#pragma unroll
    for (int j = 0; j < 8; j++) dst[tid + j * 256] = src[tid + j * 256];
    __syncthreads();

    {
        int d = tid & 127, kh = tid >> 7;
        int kb = kh * 256;
        float acc[16];
#pragma unroll
        for (int gg = 0; gg < 16; gg++) acc[gg] = 0.0f;
        for (int k = 0; k < 256; k += 2) {
            float w0 = W_m[(kb + k) * DD + d];
            float w1 = W_m[(kb + k + 1) * DD + d];
#pragma unroll
            for (int gg = 0; gg < 16; gg++) {
                float2 hv = *(const float2*)&h_s[gg][kb + k];
                acc[gg] += w0 * hv.x + w1 * hv.y;
            }
        }
#pragma unroll
        for (int gg = 0; gg < 16; gg++) red[kh][gg][d] = acc[gg];
    }
    __syncthreads();
#pragma unroll
    for (int j = 0; j < 8; j++) {
        int e = tid + j * 256;
        int gg = e >> 7, dd = e & 127;
        d_u[(g0 + gg) * DD + dd] = red[0][gg][dd] + red[1][gg][dd];
    }
    {
        int w = tid >> 5, lane = tid & 31;
#pragma unroll
        for (int j = 0; j < 2; j++) {
            int gg = w * 2 + j;
            float p = 0.0f;
            for (int k = lane; k < HH; k += 32) p += b_m[k] * h_s[gg][k];
            p += __shfl_xor_sync(0xffffffffu, p, 16);
            p += __shfl_xor_sync(0xffffffffu, p, 8);
            p += __shfl_xor_sync(0xffffffffu, p, 4);
            p += __shfl_xor_sync(0xffffffffu, p, 2);
            p += __shfl_xor_sync(0xffffffffu, p, 1);
            if (lane == 0) d_beta[g0 + gg] = p;
        }
    }
}

// ------- fused attention: online softmax, 4 nodes per warp iteration ---------
__global__ __launch_bounds__(256) void attention_fused(int use_u0) {
    int g = blockIdx.x;
    int s0 = d_start[g], s1 = d_start[g + 1];
    __shared__ __align__(16) float u_s[128];
    __shared__ __align__(16) float wacc[8][128];
    __shared__ float wm_s[8], wS_s[8], fac_s[8];
    __shared__ float inv_s;
    int tid = threadIdx.x, lane = tid & 31, warp = tid >> 5;

    if (tid < 128) u_s[tid] = use_u0 ? d_u0[tid] : d_u[g * DD + tid];
    float beta = use_u0 ? d_beta0[0] : d_beta[g];
    __syncthreads();

    float4 uv = ((const float4*)u_s)[lane];
    float m = -3.4e38f, S = 0.0f;
    float4 acc = make_float4(0.f, 0.f, 0.f, 0.f);

    for (int base = s0 + warp * 4; base < s1; base += 32) {
        float4 fv[4];
        float e[4];
#pragma unroll
        for (int j = 0; j < 4; j++) {
            int n = base + j;
            if (n < s1) {
                uint2 raw = *(const uint2*)(d_fh + (size_t)n * DD + lane * 4);
                float2 f01 = __half22float2(*(__half2*)&raw.x);
                float2 f23 = __half22float2(*(__half2*)&raw.y);
                fv[j] = make_float4(f01.x, f01.y, f23.x, f23.y);
            } else {
                fv[j] = make_float4(0.f, 0.f, 0.f, 0.f);
            }
            e[j] = fv[j].x * uv.x + fv[j].y * uv.y + fv[j].z * uv.z + fv[j].w * uv.w;
        }
#pragma unroll
        for (int j = 0; j < 4; j++) {
            e[j] += __shfl_xor_sync(0xffffffffu, e[j], 16);
            e[j] += __shfl_xor_sync(0xffffffffu, e[j], 8);
            e[j] += __shfl_xor_sync(0xffffffffu, e[j], 4);
            e[j] += __shfl_xor_sync(0xffffffffu, e[j], 2);
            e[j] += __shfl_xor_sync(0xffffffffu, e[j], 1);
        }
#pragma unroll
        for (int j = 0; j < 4; j++)
            e[j] = (base + j < s1) ? e[j] + beta : -3.0e38f;

        float m4 = fmaxf(fmaxf(e[0], e[1]), fmaxf(e[2], e[3]));
        float w0 = __expf(e[0] - m4), w1 = __expf(e[1] - m4);
        float w2 = __expf(e[2] - m4), w3 = __expf(e[3] - m4);
        float S4 = (w0 + w1) + (w2 + w3);
        float4 a4;
        a4.x = w0 * fv[0].x + w1 * fv[1].x + w2 * fv[2].x + w3 * fv[3].x;
        a4.y = w0 * fv[0].y + w1 * fv[1].y + w2 * fv[2].y + w3 * fv[3].y;
        a4.z = w0 * fv[0].z + w1 * fv[1].z + w2 * fv[2].z + w3 * fv[3].z;
        a4.w = w0 * fv[0].w + w1 * fv[1].w + w2 * fv[2].w + w3 * fv[3].w;

        float mn = fmaxf(m, m4);
        float al = __expf(m - mn);
        float bl = __expf(m4 - mn);
        S = S * al + S4 * bl;
        acc.x = acc.x * al + a4.x * bl;
        acc.y = acc.y * al + a4.y * bl;
        acc.z = acc.z * al + a4.z * bl;
        acc.w = acc.w * al + a4.w * bl;
        m = mn;
    }
    if (lane == 0) { wm_s[warp] = m; wS_s[warp] = S; }
    ((float4*)wacc[warp])[lane] = acc;
    __syncthreads();

    if (tid == 0) {
        float M = -3.4e38f;
#pragma unroll
        for (int w = 0; w < 8; w++)
            if (wS_s[w] > 0.0f) M = fmaxf(M, wm_s[w]);
        float Z = 0.0f;
#pragma unroll
        for (int w = 0; w < 8; w++) {
            float sc = (wS_s[w] > 0.0f) ? __expf(wm_s[w] - M) : 0.0f;
            fac_s[w] = sc;
            Z += sc * wS_s[w];
        }
        float inv = 1.0f / (Z + 1e-7f);
        inv_s = inv;
        d_tg[g] = Z * inv;
    }
    __syncthreads();

    if (tid < 128) {
        float inv = inv_s;
        float s = 0.0f;
#pragma unroll
        for (int w = 0; w < 8; w++) s += wacc[w][tid] * fac_s[w];
        d_s[g * DD + tid] = s * inv;
    }
}

// ---- r_g = W_m s_g + t_g b_m (8 graphs / block); blocks>=256 do gbias -------
__global__ __launch_bounds__(512) void compute_r(const float* __restrict__ b_m,
                                                 float* __restrict__ out,
                                                 int wout, int wxh) {
    int tid = threadIdx.x;
    if (blockIdx.x >= 256) {
        // gbias (t=0 launch only): gbias4f[nj] = bias4f[nj] + h0 . Wch[nj]
        int w = tid >> 5, lane = tid & 31;
        int nj = (blockIdx.x - 256) * 16 + w;
        const __half2* w2 = (const __half2*)(d_Wch + (size_t)nj * K2);
        const float2* h02 = (const float2*)d_h0;
        float p = 0.0f;
#pragma unroll
        for (int i = lane; i < HH / 2; i += 32) {
            float2 wf = __half22float2(w2[i]);
            float2 hf = h02[i];
            p += wf.x * hf.x + wf.y * hf.y;
        }
        p += __shfl_xor_sync(0xffffffffu, p, 16);
        p += __shfl_xor_sync(0xffffffffu, p, 8);
        p += __shfl_xor_sync(0xffffffffu, p, 4);
        p += __shfl_xor_sync(0xffffffffu, p, 2);
        p += __shfl_xor_sync(0xffffffffu, p, 1);
        if (lane == 0) d_gbias4f[nj] = d_bias4f[nj] + p;
        return;
    }
    int g0 = blockIdx.x * 8;
    int k = tid;                                      // 0..511
    __shared__ float ss[8][128];
    {
        int i = k;        ss[i >> 7][i & 127] = d_s[(g0 + (i >> 7)) * DD + (i & 127)];
        int i2 = k + 512; ss[i2 >> 7][i2 & 127] = d_s[(g0 + (i2 >> 7)) * DD + (i2 & 127)];
    }
    __syncthreads();
    float bm = b_m[k];
    float acc[8];
#pragma unroll
    for (int gg = 0; gg < 8; gg++) acc[gg] = d_tg[g0 + gg] * bm;
    for (int d = 0; d < DD; d++) {
        float w = d_Wmt[d * HH + k];
#pragma unroll
        for (int gg = 0; gg < 8; gg++) acc[gg] += w * ss[gg][d];
    }
#pragma unroll
    for (int gg = 0; gg < 8; gg++) {
        if (wxh) d_xh[(g0 + gg) * K2 + HH + k] = __float2half(acc[gg]);
        if (wout) out[(g0 + gg) * K2 + HH + k] = acc[gg];
    }
}

// ------------------------------ launcher ------------------------------------
extern "C" void kernel_launch(void* const* d_in, const int* in_sizes, int n_in,
                              void* d_out, int out_size) {
    const float* features = (const float*)d_in[0];
    const int*   gi       = (const int*)d_in[1];
    const float* W_m      = (const float*)d_in[2];
    const float* b_m      = (const float*)d_in[3];
    const float* W_ih     = (const float*)d_in[4];
    const float* W_hh     = (const float*)d_in[5];
    const float* b_ih     = (const float*)d_in[6];
    const float* b_hh     = (const float*)d_in[7];
    float* out = (float*)d_out;

    cudaFuncSetAttribute(gemm_lstm<512, 512, true>,
                         cudaFuncAttributeMaxDynamicSharedMemorySize, GEMM_SMEM);
    cudaFuncSetAttribute(gemm_lstm<0, 1024, false>,
                         cudaFuncAttributeMaxDynamicSharedMemorySize, GEMM_SMEM);

    prep_all<<<PREP_BLOCKS, 256>>>(features, W_ih, W_hh, b_ih, b_hh, W_m, b_m, gi);

    // t = 0: shared u0/beta0 (init0 inside prep_all)
    attention_fused<<<GG, 256>>>(1);
    compute_r<<<384, 512>>>(b_m, out, 0, 1);          // + gbias in blocks >=256

    // t = 1: K=512 GEMM over r only (h0 folded into gbias), LSTM in epilogue
    gemm_lstm<512, 512, true><<<dim3(H4 / 256, GG / 128), 256, GEMM_SMEM>>>(out);
    u_beta<<<GG / 16, 256>>>(W_m, b_m);
    attention_fused<<<GG, 256>>>(0);
    compute_r<<<256, 512>>>(b_m, out, 0, 1);

    // t = 2: full K=1024 GEMM, LSTM in epilogue writes final h to out
    gemm_lstm<0, 1024, false><<<dim3(H4 / 256, GG / 128), 256, GEMM_SMEM>>>(out);
    u_beta<<<GG / 16, 256>>>(W_m, b_m);
    attention_fused<<<GG, 256>>>(0);
    compute_r<<<256, 512>>>(b_m, out, 1, 0);
}